// round 12
// baseline (speedup 1.0000x reference)
#include <cuda_runtime.h>
#include <math.h>
#include <stdint.h>

#define N_PIX (768*768)          // 589824
#define D     256
#define C     21
#define P     64                 // pixels per tile
#define NTILES (N_PIX / P)       // 9216
#define TPB   1024
#define GRID  148
#define PITCH 68                 // floats per A row (bank-conflict-free)
#define PITCH4 17
#define NB    24                 // padded classes (3 n-blocks)
#define NSTAGE 3

// ---------------- global scratch (zero-initialized at load) ----------------
__device__ float    g_sums[C * D];
__device__ int      g_counts[C];
__device__ unsigned g_done;

// ---------------- PTX helpers ----------------
__device__ __forceinline__ unsigned s2u(const void* p) {
    return (unsigned)__cvta_generic_to_shared(p);
}
__device__ __forceinline__ void bulk_cp(void* s, const void* g, unsigned bytes, unsigned mbar) {
    asm volatile("cp.async.bulk.shared::cluster.global.mbarrier::complete_tx::bytes "
                 "[%0], [%1], %2, [%3];\n"
                 :: "r"(s2u(s)), "l"(g), "r"(bytes), "r"(mbar) : "memory");
}
__device__ __forceinline__ void mbar_init(unsigned mbar, unsigned cnt) {
    asm volatile("mbarrier.init.shared.b64 [%0], %1;\n" :: "r"(mbar), "r"(cnt) : "memory");
}
__device__ __forceinline__ void mbar_expect(unsigned mbar, unsigned tx) {
    asm volatile("mbarrier.arrive.expect_tx.shared.b64 _, [%0], %1;\n"
                 :: "r"(mbar), "r"(tx) : "memory");
}
__device__ __forceinline__ void mbar_wait(unsigned mbar, unsigned ph) {
    unsigned done;
    asm volatile("{\n\t.reg .pred p;\n\t"
                 "mbarrier.try_wait.parity.acquire.cta.shared::cta.b64 p, [%1], %2;\n\t"
                 "selp.b32 %0, 1, 0, p;\n\t}"
                 : "=r"(done) : "r"(mbar), "r"(ph) : "memory");
    if (!done) {
        asm volatile("{\n\t.reg .pred P1;\n\t"
                     "WL_%=:\n\t"
                     "mbarrier.try_wait.parity.acquire.cta.shared::cta.b64 P1, [%0], %1, 0x989680;\n\t"
                     "@P1 bra.uni WD_%=;\n\t"
                     "bra.uni WL_%=;\n\t"
                     "WD_%=:\n\t}"
                     :: "r"(mbar), "r"(ph) : "memory");
    }
}
__device__ __forceinline__ void mma_tf32(float c[4], unsigned a0, unsigned a1,
                                         unsigned a2, unsigned a3,
                                         unsigned b0, unsigned b1) {
    asm volatile("mma.sync.aligned.m16n8k8.row.col.f32.tf32.tf32.f32 "
                 "{%0,%1,%2,%3}, {%4,%5,%6,%7}, {%8,%9}, {%0,%1,%2,%3};\n"
                 : "+f"(c[0]), "+f"(c[1]), "+f"(c[2]), "+f"(c[3])
                 : "r"(a0), "r"(a1), "r"(a2), "r"(a3), "r"(b0), "r"(b1));
}

// ---------------- smem layout (floats), total 57704 floats = 230816 B ----------------
// bufA : 3 * 256*68 = 52224 (204 KB)   3-stage A tiles [dim][pix], pitch-68
// slab : 3 * 64     = 192              labels
// nred : 4096                          SS partials  (ALIASED by WT[24][68] = 1632)
// nred2: 1024 / aux2: 128 / scnt: 32 / mbar: 8
#define SM_BUFA  0
#define SM_SLAB  (NSTAGE*D*PITCH)
#define SM_NRED  (SM_SLAB + NSTAGE*P)
#define SM_WT    SM_NRED
#define SM_NRED2 (SM_NRED + 4096)
#define SM_AUX   (SM_NRED2 + 1024)
#define SM_SCNT  (SM_AUX + 2*P)
#define SM_MBAR  (SM_SCNT + 32)
#define SM_TOTAL_FLOATS (SM_MBAR + 8)
#define SMEM_BYTES (SM_TOTAL_FLOATS * 4)

#define TILE_TX ((D + 1) * P * 4)     // 65792 bytes

__device__ __forceinline__ void issue_tile(const float* __restrict__ feat,
                                           const int* __restrict__ lab,
                                           float* bufA, int* slab, unsigned mbar,
                                           int b, int tile, int t) {
    const int p0 = tile * P;
    if (t == TPB - 1) mbar_expect(mbar, TILE_TX);
    if (t < D) {
        bulk_cp(bufA + b * (D * PITCH) + t * PITCH, feat + (size_t)t * N_PIX + p0,
                P * 4, mbar);
    } else if (t == D) {
        bulk_cp(slab + b * P, lab + p0, P * 4, mbar);
    }
}

// ---------------- single fused kernel ----------------
__global__ __launch_bounds__(TPB, 1)
void fused_kernel(const float* __restrict__ feat, const int* __restrict__ lab,
                  const float* __restrict__ proto, float* __restrict__ out) {
    extern __shared__ float smem[];
    float*  bufA = smem + SM_BUFA;
    int*    slab = (int*)(smem + SM_SLAB);
    float*  nred = smem + SM_NRED;
    float*  wt   = smem + SM_WT;          // aliases nred
    float*  nred2= smem + SM_NRED2;
    float2* aux2 = (float2*)(smem + SM_AUX);
    int*    scnt = (int*)(smem + SM_SCNT);
    const unsigned mb0 = s2u(smem + SM_MBAR);

    const int t = threadIdx.x;
    const int l = t & 31, w = t >> 5;
    const int g = l >> 2, tk = l & 3;

    if (t < C) scnt[t] = 0;
    if (t == 0) {
        mbar_init(mb0, 1); mbar_init(mb0 + 8, 1); mbar_init(mb0 + 16, 1);
        asm volatile("fence.proxy.async.shared::cta;\n" ::: "memory");
    }
    __syncthreads();

    const int tl0 = blockIdx.x;
    issue_tile(feat, lab, bufA, slab, mb0,      0, tl0,            t);
    issue_tile(feat, lab, bufA, slab, mb0 + 8,  1, tl0 + GRID,     t);
    issue_tile(feat, lab, bufA, slab, mb0 + 16, 2, tl0 + 2*GRID,   t);  // >=62 tiles per CTA

    const int p4 = t & 15;       // SS stage1: pixel quad
    const int q  = t >> 4;       // SS stage1: dim-quad 0..63

    // MMA ownership: warps 0-15 dims 16w, pixels 0..31; warps 16-31 same dims, pixels 32..63
    const int dim0  = 16 * (w & 15);
    const int kbase = (w >> 4) * 32;

    float acc[3][4];
    #pragma unroll
    for (int n = 0; n < 3; n++)
        #pragma unroll
        for (int i = 0; i < 4; i++) acc[n][i] = 0.f;

    int b = 0; unsigned ph = 0;
    for (int tl = tl0; tl < NTILES; tl += GRID) {
        mbar_wait(mb0 + 8 * b, ph);

        const float* tbase = bufA + b * (D * PITCH);
        const int*   lb    = slab + b * P;

        // ---- SS stage 1: each thread 4 dims x 1 pixel-quad ----
        {
            const float4* tb4 = (const float4*)tbase;
            float4 ss = make_float4(0.f, 0.f, 0.f, 0.f);
            #pragma unroll
            for (int jj = 0; jj < 4; jj++) {
                float4 v = tb4[(q * 4 + jj) * PITCH4 + p4];
                ss.x += v.x * v.x; ss.y += v.y * v.y;
                ss.z += v.z * v.z; ss.w += v.w * v.w;
            }
            ((float4*)nred)[q * 16 + p4] = ss;
        }
        __syncthreads();
        // ---- SS stage 2a: fold 64 partials -> 16 ----
        {
            int p = t & 63, h = t >> 6;
            nred2[h * 64 + p] = nred[(h * 4 + 0) * 64 + p] + nred[(h * 4 + 1) * 64 + p]
                              + nred[(h * 4 + 2) * 64 + p] + nred[(h * 4 + 3) * 64 + p];
        }
        __syncthreads();
        // ---- SS stage 2b: finalize norms ----
        if (t < P) {
            float ssum = 0.f;
            #pragma unroll
            for (int h = 0; h < 16; h++) ssum += nred2[h * 64 + t];
            float inv = 1.0f / fmaxf(sqrtf(ssum), 1e-12f);
            int lv = lb[t];
            aux2[t] = make_float2(inv, __int_as_float(lv));
            atomicAdd(&scnt[lv], 1);
        }
        __syncthreads();
        // ---- build W^T [24 cls][pitch 68]: weighted one-hot (aliases nred) ----
        {
            {
                int n = t >> 6, kx = t & 63;         // idx 0..1023
                float2 a = aux2[kx];
                wt[n * PITCH + kx] = (__float_as_int(a.y) == n) ? a.x : 0.f;
            }
            if (t < NB * P - TPB) {                  // idx 1024..1535
                int idx = t + TPB;
                int n = idx >> 6, kx = idx & 63;
                float2 a = aux2[kx];
                wt[n * PITCH + kx] = (__float_as_int(a.y) == n) ? a.x : 0.f;
            }
        }
        __syncthreads();

        // ---- MMA: acc[dim, cls] += A[dim, pix] @ W ----
        {
            const float* ar0 = tbase + (dim0 + g) * PITCH;
            const float* ar1 = ar0 + 8 * PITCH;
            #pragma unroll
            for (int kk = 0; kk < 4; kk++) {
                int k0 = kbase + kk * 8;
                unsigned a0 = __float_as_uint(ar0[k0 + tk]);
                unsigned a1 = __float_as_uint(ar1[k0 + tk]);
                unsigned a2 = __float_as_uint(ar0[k0 + tk + 4]);
                unsigned a3 = __float_as_uint(ar1[k0 + tk + 4]);
                #pragma unroll
                for (int n = 0; n < 3; n++) {
                    const float* wr = wt + (8 * n + g) * PITCH;
                    unsigned b0 = __float_as_uint(wr[k0 + tk]);
                    unsigned b1 = __float_as_uint(wr[k0 + tk + 4]);
                    mma_tf32(acc[n], a0, a1, a2, a3, b0, b1);
                }
            }
        }
        __syncthreads();

        // ---- refill this buffer with tile tl + 3*GRID ----
        int nt = tl + NSTAGE * GRID;
        if (nt < NTILES)
            issue_tile(feat, lab, bufA, slab, mb0 + 8 * b, b, nt, t);

        if (++b == NSTAGE) { b = 0; ph ^= 1u; }
    }

    // ---- flush register accumulators ----
    {
        const int dimA = dim0 + g;
        const int dimB = dimA + 8;
        #pragma unroll
        for (int n = 0; n < 3; n++) {
            int cls0 = 8 * n + 2 * tk;
            int cls1 = cls0 + 1;
            if (cls0 < C) {
                atomicAdd(&g_sums[cls0 * D + dimA], acc[n][0]);
                atomicAdd(&g_sums[cls0 * D + dimB], acc[n][2]);
            }
            if (cls1 < C) {
                atomicAdd(&g_sums[cls1 * D + dimA], acc[n][1]);
                atomicAdd(&g_sums[cls1 * D + dimB], acc[n][3]);
            }
        }
    }
    if (t < C) atomicAdd(&g_counts[t], scnt[t]);
    __syncthreads();

    // ---- last block does the finalize ----
    __shared__ unsigned s_last;
    if (t == 0) {
        __threadfence();
        s_last = (atomicAdd(&g_done, 1u) == GRID - 1) ? 1u : 0u;
    }
    __syncthreads();
    if (!s_last) return;

    float* s_mean  = smem;                 // C*D
    float* s_proto = smem + C * D;         // C*D
    float* s_logit = smem + 2 * C * D;     // C*C

    for (int i = t; i < C * D; i += TPB) {
        int c = i / D;
        float cnt = (float)g_counts[c];
        s_mean[i]  = g_sums[i] / fmaxf(cnt, 1.0f);
        s_proto[i] = proto[i];
    }
    __syncthreads();

    for (int r = w; r < C; r += TPB / 32) {
        for (int jc = 0; jc < C; jc++) {
            float sacc = 0.f;
            #pragma unroll
            for (int kk = 0; kk < 8; kk++)
                sacc += s_mean[r * D + l + 32 * kk] * s_proto[jc * D + l + 32 * kk];
            #pragma unroll
            for (int o = 16; o; o >>= 1) sacc += __shfl_xor_sync(0xffffffffu, sacc, o);
            if (l == 0) s_logit[r * C + jc] = sacc * 10.0f;   // / TEMP (0.1)
        }
    }
    __syncthreads();

    if (t < 32) {
        float v = 0.f;
        if (t >= 1 && t < C) {
            float mx = -INFINITY;
            for (int jc = 0; jc < C; jc++) mx = fmaxf(mx, s_logit[t * C + jc]);
            float den = 0.f;
            for (int jc = 1; jc < C; jc++) den += expf(s_logit[t * C + jc] - mx);
            v = logf(den) - (s_logit[t * C + t] - mx);
        }
        #pragma unroll
        for (int o = 16; o; o >>= 1) v += __shfl_xor_sync(0xffffffffu, v, o);
        if (t == 0) out[0] = v / (float)(C - 1);
    }
    __syncthreads();

    // ---- reset globals for next graph replay ----
    for (int i = t; i < C * D; i += TPB) g_sums[i] = 0.f;
    if (t < C) g_counts[t] = 0;
    if (t == 0) g_done = 0;
}

// ---------------- launch ----------------
extern "C" void kernel_launch(void* const* d_in, const int* in_sizes, int n_in,
                              void* d_out, int out_size) {
    const float* feat  = (const float*)d_in[0];   // [1,256,768,768]
    const float* proto = (const float*)d_in[1];   // [21,256]
    // d_in[2] = outputs (unused by the loss)
    const int*   lab   = (const int*)d_in[3];     // [1,1,768,768]
    float* out = (float*)d_out;

    cudaFuncSetAttribute(fused_kernel,
                         cudaFuncAttributeMaxDynamicSharedMemorySize, SMEM_BYTES);

    fused_kernel<<<GRID, TPB, SMEM_BYTES>>>(feat, lab, proto, out);
}

// round 14
// speedup vs baseline: 1.2647x; 1.2647x over previous
#include <cuda_runtime.h>
#include <cuda.h>
#include <math.h>
#include <stdint.h>

#define N_PIX (768*768)          // 589824
#define D     256
#define C     21
#define P     64                 // pixels per tile
#define NTILES (N_PIX / P)       // 9216
#define TPB   1024
#define GRID  148
#define NB    24                 // padded classes (3 n-blocks)
#define NSTAGE 3
#define HALF_FLOATS 8192         // 256 rows x 32 floats (32 KB)
#define TILE_FLOATS (2*HALF_FLOATS)

// ---------------- global scratch (zero-initialized at load) ----------------
__device__ float    g_sums[C * D];
__device__ int      g_counts[C];
__device__ unsigned g_done;

// ---------------- PTX helpers ----------------
__device__ __forceinline__ unsigned s2u(const void* p) {
    return (unsigned)__cvta_generic_to_shared(p);
}
__device__ __forceinline__ void bulk_cp(void* s, const void* g, unsigned bytes, unsigned mbar) {
    asm volatile("cp.async.bulk.shared::cluster.global.mbarrier::complete_tx::bytes "
                 "[%0], [%1], %2, [%3];\n"
                 :: "r"(s2u(s)), "l"(g), "r"(bytes), "r"(mbar) : "memory");
}
__device__ __forceinline__ void tma2d(unsigned sdst, const CUtensorMap* map,
                                      int x, int y, unsigned mbar) {
    asm volatile("cp.async.bulk.tensor.2d.shared::cta.global.tile.mbarrier::complete_tx::bytes "
                 "[%0], [%1, {%2, %3}], [%4];\n"
                 :: "r"(sdst), "l"(map), "r"(x), "r"(y), "r"(mbar) : "memory");
}
__device__ __forceinline__ void mbar_init(unsigned mbar, unsigned cnt) {
    asm volatile("mbarrier.init.shared.b64 [%0], %1;\n" :: "r"(mbar), "r"(cnt) : "memory");
}
__device__ __forceinline__ void mbar_expect(unsigned mbar, unsigned tx) {
    asm volatile("mbarrier.arrive.expect_tx.shared.b64 _, [%0], %1;\n"
                 :: "r"(mbar), "r"(tx) : "memory");
}
__device__ __forceinline__ void mbar_wait(unsigned mbar, unsigned ph) {
    unsigned done;
    asm volatile("{\n\t.reg .pred p;\n\t"
                 "mbarrier.try_wait.parity.acquire.cta.shared::cta.b64 p, [%1], %2;\n\t"
                 "selp.b32 %0, 1, 0, p;\n\t}"
                 : "=r"(done) : "r"(mbar), "r"(ph) : "memory");
    if (!done) {
        asm volatile("{\n\t.reg .pred P1;\n\t"
                     "WL_%=:\n\t"
                     "mbarrier.try_wait.parity.acquire.cta.shared::cta.b64 P1, [%0], %1, 0x989680;\n\t"
                     "@P1 bra.uni WD_%=;\n\t"
                     "bra.uni WL_%=;\n\t"
                     "WD_%=:\n\t}"
                     :: "r"(mbar), "r"(ph) : "memory");
    }
}
__device__ __forceinline__ void mma_tf32(float c[4], unsigned a0, unsigned a1,
                                         unsigned a2, unsigned a3,
                                         unsigned b0, unsigned b1) {
    asm volatile("mma.sync.aligned.m16n8k8.row.col.f32.tf32.tf32.f32 "
                 "{%0,%1,%2,%3}, {%4,%5,%6,%7}, {%8,%9}, {%0,%1,%2,%3};\n"
                 : "+f"(c[0]), "+f"(c[1]), "+f"(c[2]), "+f"(c[3])
                 : "r"(a0), "r"(a1), "r"(a2), "r"(a3), "r"(b0), "r"(b1));
}

// ================== shared finalize (device function) ==================
__device__ void finalize_and_reset(float* smem, const float* __restrict__ proto,
                                   float* __restrict__ out, int t, int l, int w) {
    float* s_mean  = smem;                 // C*D
    float* s_proto = smem + C * D;         // C*D
    float* s_logit = smem + 2 * C * D;     // C*C

    for (int i = t; i < C * D; i += TPB) {
        int c = i / D;
        float cnt = (float)g_counts[c];
        s_mean[i]  = g_sums[i] / fmaxf(cnt, 1.0f);
        s_proto[i] = proto[i];
    }
    __syncthreads();

    for (int r = w; r < C; r += TPB / 32) {
        for (int jc = 0; jc < C; jc++) {
            float sacc = 0.f;
            #pragma unroll
            for (int kk = 0; kk < 8; kk++)
                sacc += s_mean[r * D + l + 32 * kk] * s_proto[jc * D + l + 32 * kk];
            #pragma unroll
            for (int o = 16; o; o >>= 1) sacc += __shfl_xor_sync(0xffffffffu, sacc, o);
            if (l == 0) s_logit[r * C + jc] = sacc * 10.0f;   // / TEMP (0.1)
        }
    }
    __syncthreads();

    if (t < 32) {
        float v = 0.f;
        if (t >= 1 && t < C) {
            float mx = -INFINITY;
            for (int jc = 0; jc < C; jc++) mx = fmaxf(mx, s_logit[t * C + jc]);
            float den = 0.f;
            for (int jc = 1; jc < C; jc++) den += expf(s_logit[t * C + jc] - mx);
            v = logf(den) - (s_logit[t * C + t] - mx);
        }
        #pragma unroll
        for (int o = 16; o; o >>= 1) v += __shfl_xor_sync(0xffffffffu, v, o);
        if (t == 0) out[0] = v / (float)(C - 1);
    }
    __syncthreads();

    for (int i = t; i < C * D; i += TPB) g_sums[i] = 0.f;
    if (t < C) g_counts[t] = 0;
    if (t == 0) g_done = 0;
}

// ============================================================
//  TMA-path kernel (SW128 tiles: 2 halves of [256 rows x 32f])
// ============================================================
#define SM_BUFA  0
#define SM_SLAB  (NSTAGE*TILE_FLOATS)
#define SM_NRED  (SM_SLAB + NSTAGE*P)
#define SM_WT    SM_NRED
#define WPITCH   68
#define SM_NRED2 (SM_NRED + 4096)
#define SM_AUX   (SM_NRED2 + 1024)
#define SM_SCNT  (SM_AUX + 2*P)
#define SM_MBAR  (SM_SCNT + 32)
#define SM_TOTAL_FLOATS (SM_MBAR + 8)
#define SMEM_BYTES (SM_TOTAL_FLOATS * 4)

#define TILE_TX (2*32768 + P*4)       // 65792 bytes

__device__ __forceinline__ void issue_tile_tma(const CUtensorMap* map,
                                               const int* __restrict__ lab,
                                               float* bufA, int* slab, unsigned mbar,
                                               int b, int tile, int t) {
    if (t == TPB - 1) {
        const int p0 = tile * P;
        mbar_expect(mbar, TILE_TX);
        unsigned d0 = s2u(bufA + b * TILE_FLOATS);
        tma2d(d0,          map, p0,      0, mbar);
        tma2d(d0 + 32768,  map, p0 + 32, 0, mbar);
        bulk_cp(slab + b * P, lab + p0, P * 4, mbar);
    }
}

__global__ __launch_bounds__(TPB, 1)
void fused_tma(const __grid_constant__ CUtensorMap tmap,
               const int* __restrict__ lab,
               const float* __restrict__ proto, float* __restrict__ out) {
    extern __shared__ __align__(1024) float smem[];
    float*  bufA = smem + SM_BUFA;
    int*    slab = (int*)(smem + SM_SLAB);
    float*  nred = smem + SM_NRED;
    float*  wt   = smem + SM_WT;          // aliases nred
    float*  nred2= smem + SM_NRED2;
    float2* aux2 = (float2*)(smem + SM_AUX);
    int*    scnt = (int*)(smem + SM_SCNT);
    const unsigned mb0 = s2u(smem + SM_MBAR);

    const int t = threadIdx.x;
    const int l = t & 31, w = t >> 5;
    const int g = l >> 2, tk = l & 3;

    if (t < C) scnt[t] = 0;
    if (t == 0) {
        mbar_init(mb0, 1); mbar_init(mb0 + 8, 1); mbar_init(mb0 + 16, 1);
        asm volatile("fence.proxy.async.shared::cta;\n" ::: "memory");
    }
    __syncthreads();

    const int tl0 = blockIdx.x;
    issue_tile_tma(&tmap, lab, bufA, slab, mb0,      0, tl0,          t);
    issue_tile_tma(&tmap, lab, bufA, slab, mb0 + 8,  1, tl0 + GRID,   t);
    issue_tile_tma(&tmap, lab, bufA, slab, mb0 + 16, 2, tl0 + 2*GRID, t); // >=62 tiles/CTA

    const int p4 = t & 15;
    const int q  = t >> 4;
    const int hss = p4 >> 3;
    const int c4s = (p4 & 7) * 4;

    const int dim0  = 16 * (w & 15);
    const int kbase = (w >> 4) * 32;
    const int rA    = dim0 + g;
    const unsigned xorv = (unsigned)((rA & 7) << 2);

    float acc[3][4];
    #pragma unroll
    for (int n = 0; n < 3; n++)
        #pragma unroll
        for (int i = 0; i < 4; i++) acc[n][i] = 0.f;

    int b = 0; unsigned ph = 0;
    for (int tl = tl0; tl < NTILES; tl += GRID) {
        mbar_wait(mb0 + 8 * b, ph);

        const float* tbase = bufA + b * TILE_FLOATS;
        const int*   lb    = slab + b * P;

        {   // SS stage 1 (swizzled reads)
            const float* hb = tbase + hss * HALF_FLOATS;
            float4 ss = make_float4(0.f, 0.f, 0.f, 0.f);
            #pragma unroll
            for (int jj = 0; jj < 4; jj++) {
                int r = q * 4 + jj;
                float4 v = *(const float4*)(hb + r * 32 + (c4s ^ ((r & 7) << 2)));
                ss.x += v.x * v.x; ss.y += v.y * v.y;
                ss.z += v.z * v.z; ss.w += v.w * v.w;
            }
            ((float4*)nred)[q * 16 + p4] = ss;
        }
        __syncthreads();
        {   // SS stage 2a
            int p = t & 63, h = t >> 6;
            nred2[h * 64 + p] = nred[(h * 4 + 0) * 64 + p] + nred[(h * 4 + 1) * 64 + p]
                              + nred[(h * 4 + 2) * 64 + p] + nred[(h * 4 + 3) * 64 + p];
        }
        __syncthreads();
        if (t < P) {   // SS stage 2b
            float ssum = 0.f;
            #pragma unroll
            for (int h = 0; h < 16; h++) ssum += nred2[h * 64 + t];
            float inv = 1.0f / fmaxf(sqrtf(ssum), 1e-12f);
            int lv = lb[t];
            aux2[t] = make_float2(inv, __int_as_float(lv));
            atomicAdd(&scnt[lv], 1);
        }
        __syncthreads();
        {   // build W^T
            {
                int n = t >> 6, kx = t & 63;
                float2 a = aux2[kx];
                wt[n * WPITCH + kx] = (__float_as_int(a.y) == n) ? a.x : 0.f;
            }
            if (t < NB * P - TPB) {
                int idx = t + TPB;
                int n = idx >> 6, kx = idx & 63;
                float2 a = aux2[kx];
                wt[n * WPITCH + kx] = (__float_as_int(a.y) == n) ? a.x : 0.f;
            }
        }
        __syncthreads();

        {   // MMA with swizzled A reads
            const float* baseR  = tbase + rA * 32;
            const float* baseR8 = tbase + (rA + 8) * 32;
            #pragma unroll
            for (int kk = 0; kk < 4; kk++) {
                int k0  = kbase + kk * 8;
                int hof = (k0 >> 5) * HALF_FLOATS;
                int c   = k0 & 31;
                unsigned c1 = (unsigned)((c + tk) ^ (int)xorv) + hof;
                unsigned c2 = (unsigned)((c + tk + 4) ^ (int)xorv) + hof;
                unsigned a0 = __float_as_uint(baseR[c1]);
                unsigned a1 = __float_as_uint(baseR8[c1]);
                unsigned a2 = __float_as_uint(baseR[c2]);
                unsigned a3 = __float_as_uint(baseR8[c2]);
                #pragma unroll
                for (int n = 0; n < 3; n++) {
                    const float* wr = wt + (8 * n + g) * WPITCH;
                    unsigned b0 = __float_as_uint(wr[k0 + tk]);
                    unsigned b1 = __float_as_uint(wr[k0 + tk + 4]);
                    mma_tf32(acc[n], a0, a1, a2, a3, b0, b1);
                }
            }
        }
        __syncthreads();

        int nt = tl + NSTAGE * GRID;
        if (nt < NTILES)
            issue_tile_tma(&tmap, lab, bufA, slab, mb0 + 8 * b, b, nt, t);

        if (++b == NSTAGE) { b = 0; ph ^= 1u; }
    }

    {   // flush
        const int dimA = rA, dimB = rA + 8;
        #pragma unroll
        for (int n = 0; n < 3; n++) {
            int cls0 = 8 * n + 2 * tk, cls1 = cls0 + 1;
            if (cls0 < C) {
                atomicAdd(&g_sums[cls0 * D + dimA], acc[n][0]);
                atomicAdd(&g_sums[cls0 * D + dimB], acc[n][2]);
            }
            if (cls1 < C) {
                atomicAdd(&g_sums[cls1 * D + dimA], acc[n][1]);
                atomicAdd(&g_sums[cls1 * D + dimB], acc[n][3]);
            }
        }
    }
    if (t < C) atomicAdd(&g_counts[t], scnt[t]);
    __syncthreads();

    if (t == 0) {
        __threadfence();
        scnt[31] = (atomicAdd(&g_done, 1u) == GRID - 1) ? 1 : 0;
    }
    __syncthreads();
    if (!scnt[31]) return;
    finalize_and_reset(smem, proto, out, t, l, w);
}

// ============================================================
//  Fallback kernel: round-12 bulk-copy version (proven pass)
// ============================================================
#define FPITCH 68
#define FPITCH4 17
#define FB_BUFA  0
#define FB_SLAB  (NSTAGE*D*FPITCH)
#define FB_NRED  (FB_SLAB + NSTAGE*P)
#define FB_WT    FB_NRED
#define FB_NRED2 (FB_NRED + 4096)
#define FB_AUX   (FB_NRED2 + 1024)
#define FB_SCNT  (FB_AUX + 2*P)
#define FB_MBAR  (FB_SCNT + 32)
#define FB_TOTAL_FLOATS (FB_MBAR + 8)
#define FB_SMEM_BYTES (FB_TOTAL_FLOATS * 4)
#define FB_TILE_TX ((D + 1) * P * 4)

__device__ __forceinline__ void issue_tile_bulk(const float* __restrict__ feat,
                                                const int* __restrict__ lab,
                                                float* bufA, int* slab, unsigned mbar,
                                                int b, int tile, int t) {
    const int p0 = tile * P;
    if (t == TPB - 1) mbar_expect(mbar, FB_TILE_TX);
    if (t < D) {
        bulk_cp(bufA + b * (D * FPITCH) + t * FPITCH, feat + (size_t)t * N_PIX + p0,
                P * 4, mbar);
    } else if (t == D) {
        bulk_cp(slab + b * P, lab + p0, P * 4, mbar);
    }
}

__global__ __launch_bounds__(TPB, 1)
void fused_bulk(const float* __restrict__ feat, const int* __restrict__ lab,
                const float* __restrict__ proto, float* __restrict__ out) {
    extern __shared__ __align__(1024) float smem[];
    float*  bufA = smem + FB_BUFA;
    int*    slab = (int*)(smem + FB_SLAB);
    float*  nred = smem + FB_NRED;
    float*  wt   = smem + FB_WT;
    float*  nred2= smem + FB_NRED2;
    float2* aux2 = (float2*)(smem + FB_AUX);
    int*    scnt = (int*)(smem + FB_SCNT);
    const unsigned mb0 = s2u(smem + FB_MBAR);

    const int t = threadIdx.x;
    const int l = t & 31, w = t >> 5;
    const int g = l >> 2, tk = l & 3;

    if (t < C) scnt[t] = 0;
    if (t == 0) {
        mbar_init(mb0, 1); mbar_init(mb0 + 8, 1); mbar_init(mb0 + 16, 1);
        asm volatile("fence.proxy.async.shared::cta;\n" ::: "memory");
    }
    __syncthreads();

    const int tl0 = blockIdx.x;
    issue_tile_bulk(feat, lab, bufA, slab, mb0,      0, tl0,          t);
    issue_tile_bulk(feat, lab, bufA, slab, mb0 + 8,  1, tl0 + GRID,   t);
    issue_tile_bulk(feat, lab, bufA, slab, mb0 + 16, 2, tl0 + 2*GRID, t);

    const int p4 = t & 15;
    const int q  = t >> 4;
    const int dim0  = 16 * (w & 15);
    const int kbase = (w >> 4) * 32;

    float acc[3][4];
    #pragma unroll
    for (int n = 0; n < 3; n++)
        #pragma unroll
        for (int i = 0; i < 4; i++) acc[n][i] = 0.f;

    int b = 0; unsigned ph = 0;
    for (int tl = tl0; tl < NTILES; tl += GRID) {
        mbar_wait(mb0 + 8 * b, ph);

        const float* tbase = bufA + b * (D * FPITCH);
        const int*   lb    = slab + b * P;

        {
            const float4* tb4 = (const float4*)tbase;
            float4 ss = make_float4(0.f, 0.f, 0.f, 0.f);
            #pragma unroll
            for (int jj = 0; jj < 4; jj++) {
                float4 v = tb4[(q * 4 + jj) * FPITCH4 + p4];
                ss.x += v.x * v.x; ss.y += v.y * v.y;
                ss.z += v.z * v.z; ss.w += v.w * v.w;
            }
            ((float4*)nred)[q * 16 + p4] = ss;
        }
        __syncthreads();
        {
            int p = t & 63, h = t >> 6;
            nred2[h * 64 + p] = nred[(h * 4 + 0) * 64 + p] + nred[(h * 4 + 1) * 64 + p]
                              + nred[(h * 4 + 2) * 64 + p] + nred[(h * 4 + 3) * 64 + p];
        }
        __syncthreads();
        if (t < P) {
            float ssum = 0.f;
            #pragma unroll
            for (int h = 0; h < 16; h++) ssum += nred2[h * 64 + t];
            float inv = 1.0f / fmaxf(sqrtf(ssum), 1e-12f);
            int lv = lb[t];
            aux2[t] = make_float2(inv, __int_as_float(lv));
            atomicAdd(&scnt[lv], 1);
        }
        __syncthreads();
        {
            {
                int n = t >> 6, kx = t & 63;
                float2 a = aux2[kx];
                wt[n * FPITCH + kx] = (__float_as_int(a.y) == n) ? a.x : 0.f;
            }
            if (t < NB * P - TPB) {
                int idx = t + TPB;
                int n = idx >> 6, kx = idx & 63;
                float2 a = aux2[kx];
                wt[n * FPITCH + kx] = (__float_as_int(a.y) == n) ? a.x : 0.f;
            }
        }
        __syncthreads();

        {
            const float* ar0 = tbase + (dim0 + g) * FPITCH;
            const float* ar1 = ar0 + 8 * FPITCH;
            #pragma unroll
            for (int kk = 0; kk < 4; kk++) {
                int k0 = kbase + kk * 8;
                unsigned a0 = __float_as_uint(ar0[k0 + tk]);
                unsigned a1 = __float_as_uint(ar1[k0 + tk]);
                unsigned a2 = __float_as_uint(ar0[k0 + tk + 4]);
                unsigned a3 = __float_as_uint(ar1[k0 + tk + 4]);
                #pragma unroll
                for (int n = 0; n < 3; n++) {
                    const float* wr = wt + (8 * n + g) * FPITCH;
                    unsigned b0 = __float_as_uint(wr[k0 + tk]);
                    unsigned b1 = __float_as_uint(wr[k0 + tk + 4]);
                    mma_tf32(acc[n], a0, a1, a2, a3, b0, b1);
                }
            }
        }
        __syncthreads();

        int nt = tl + NSTAGE * GRID;
        if (nt < NTILES)
            issue_tile_bulk(feat, lab, bufA, slab, mb0 + 8 * b, b, nt, t);

        if (++b == NSTAGE) { b = 0; ph ^= 1u; }
    }

    {
        const int dimA = dim0 + g, dimB = dimA + 8;
        #pragma unroll
        for (int n = 0; n < 3; n++) {
            int cls0 = 8 * n + 2 * tk, cls1 = cls0 + 1;
            if (cls0 < C) {
                atomicAdd(&g_sums[cls0 * D + dimA], acc[n][0]);
                atomicAdd(&g_sums[cls0 * D + dimB], acc[n][2]);
            }
            if (cls1 < C) {
                atomicAdd(&g_sums[cls1 * D + dimA], acc[n][1]);
                atomicAdd(&g_sums[cls1 * D + dimB], acc[n][3]);
            }
        }
    }
    if (t < C) atomicAdd(&g_counts[t], scnt[t]);
    __syncthreads();

    if (t == 0) {
        __threadfence();
        scnt[31] = (atomicAdd(&g_done, 1u) == GRID - 1) ? 1 : 0;
    }
    __syncthreads();
    if (!scnt[31]) return;
    finalize_and_reset(smem, proto, out, t, l, w);
}

// ---------------- host: encode tensor map + launch ----------------
typedef CUresult (*encode_fn_t)(CUtensorMap*, CUtensorMapDataType, cuuint32_t, void*,
                                const cuuint64_t*, const cuuint64_t*,
                                const cuuint32_t*, const cuuint32_t*,
                                CUtensorMapInterleave, CUtensorMapSwizzle,
                                CUtensorMapL2promotion, CUtensorMapFloatOOBfill);

extern "C" void kernel_launch(void* const* d_in, const int* in_sizes, int n_in,
                              void* d_out, int out_size) {
    const float* feat  = (const float*)d_in[0];   // [1,256,768,768]
    const float* proto = (const float*)d_in[1];   // [21,256]
    // d_in[2] = outputs (unused by the loss)
    const int*   lab   = (const int*)d_in[3];     // [1,1,768,768]
    float* out = (float*)d_out;

    void* fn = nullptr;
    cudaDriverEntryPointQueryResult qr;
#if CUDART_VERSION >= 12050
    cudaGetDriverEntryPointByVersion("cuTensorMapEncodeTiled", &fn, 12000,
                                     cudaEnableDefault, &qr);
#endif
    if (!fn)
        cudaGetDriverEntryPoint("cuTensorMapEncodeTiled", &fn, cudaEnableDefault, &qr);

    bool tma_ok = false;
    CUtensorMap tmap;
    if (fn) {
        cuuint64_t dims[2]    = {(cuuint64_t)N_PIX, (cuuint64_t)D};
        cuuint64_t strides[1] = {(cuuint64_t)N_PIX * 4};
        cuuint32_t box[2]     = {32u, (cuuint32_t)D};
        cuuint32_t es[2]      = {1u, 1u};
        CUresult r = ((encode_fn_t)fn)(&tmap, CU_TENSOR_MAP_DATA_TYPE_FLOAT32, 2,
                                       (void*)feat, dims, strides, box, es,
                                       CU_TENSOR_MAP_INTERLEAVE_NONE,
                                       CU_TENSOR_MAP_SWIZZLE_128B,
                                       CU_TENSOR_MAP_L2_PROMOTION_L2_128B,
                                       CU_TENSOR_MAP_FLOAT_OOB_FILL_NONE);
        tma_ok = (r == CUDA_SUCCESS);
    }

    if (tma_ok) {
        cudaFuncSetAttribute(fused_tma,
                             cudaFuncAttributeMaxDynamicSharedMemorySize, SMEM_BYTES);
        fused_tma<<<GRID, TPB, SMEM_BYTES>>>(tmap, lab, proto, out);
    } else {
        cudaFuncSetAttribute(fused_bulk,
                             cudaFuncAttributeMaxDynamicSharedMemorySize, FB_SMEM_BYTES);
        fused_bulk<<<GRID, TPB, FB_SMEM_BYTES>>>(feat, lab, proto, out);
    }
}

// round 15
// speedup vs baseline: 1.2866x; 1.0173x over previous
#include <cuda_runtime.h>
#include <cuda.h>
#include <math.h>
#include <stdint.h>

#define N_PIX (768*768)          // 589824
#define D     256
#define C     21
#define P     64                 // pixels per tile
#define NTILES (N_PIX / P)       // 9216
#define TPB   1024
#define GRID  148
#define NB    24                 // padded classes (3 n-blocks)
#define NSTAGE 3
#define HALF_FLOATS 8192         // 256 rows x 32 floats (32 KB)
#define TILE_FLOATS (2*HALF_FLOATS)
#define WPITCH 68
#define WT_FLOATS (NB*WPITCH)    // 1632

// ---------------- global scratch (zero-initialized at load) ----------------
__device__ float    g_sums[C * D];
__device__ int      g_counts[C];
__device__ unsigned g_done;

// ---------------- PTX helpers ----------------
__device__ __forceinline__ unsigned s2u(const void* p) {
    return (unsigned)__cvta_generic_to_shared(p);
}
__device__ __forceinline__ void bulk_cp(void* s, const void* g, unsigned bytes, unsigned mbar) {
    asm volatile("cp.async.bulk.shared::cluster.global.mbarrier::complete_tx::bytes "
                 "[%0], [%1], %2, [%3];\n"
                 :: "r"(s2u(s)), "l"(g), "r"(bytes), "r"(mbar) : "memory");
}
__device__ __forceinline__ void tma2d(unsigned sdst, const CUtensorMap* map,
                                      int x, int y, unsigned mbar) {
    asm volatile("cp.async.bulk.tensor.2d.shared::cta.global.tile.mbarrier::complete_tx::bytes "
                 "[%0], [%1, {%2, %3}], [%4];\n"
                 :: "r"(sdst), "l"(map), "r"(x), "r"(y), "r"(mbar) : "memory");
}
__device__ __forceinline__ void mbar_init(unsigned mbar, unsigned cnt) {
    asm volatile("mbarrier.init.shared.b64 [%0], %1;\n" :: "r"(mbar), "r"(cnt) : "memory");
}
__device__ __forceinline__ void mbar_expect(unsigned mbar, unsigned tx) {
    asm volatile("mbarrier.arrive.expect_tx.shared.b64 _, [%0], %1;\n"
                 :: "r"(mbar), "r"(tx) : "memory");
}
__device__ __forceinline__ void mbar_wait(unsigned mbar, unsigned ph) {
    unsigned done;
    asm volatile("{\n\t.reg .pred p;\n\t"
                 "mbarrier.try_wait.parity.acquire.cta.shared::cta.b64 p, [%1], %2;\n\t"
                 "selp.b32 %0, 1, 0, p;\n\t}"
                 : "=r"(done) : "r"(mbar), "r"(ph) : "memory");
    if (!done) {
        asm volatile("{\n\t.reg .pred P1;\n\t"
                     "WL_%=:\n\t"
                     "mbarrier.try_wait.parity.acquire.cta.shared::cta.b64 P1, [%0], %1, 0x989680;\n\t"
                     "@P1 bra.uni WD_%=;\n\t"
                     "bra.uni WL_%=;\n\t"
                     "WD_%=:\n\t}"
                     :: "r"(mbar), "r"(ph) : "memory");
    }
}
__device__ __forceinline__ void bar_norm() {     // named barrier: norm group (512 thr)
    asm volatile("bar.sync 1, 512;" ::: "memory");
}
__device__ __forceinline__ void mma_tf32(float c[4], unsigned a0, unsigned a1,
                                         unsigned a2, unsigned a3,
                                         unsigned b0, unsigned b1) {
    asm volatile("mma.sync.aligned.m16n8k8.row.col.f32.tf32.tf32.f32 "
                 "{%0,%1,%2,%3}, {%4,%5,%6,%7}, {%8,%9}, {%0,%1,%2,%3};\n"
                 : "+f"(c[0]), "+f"(c[1]), "+f"(c[2]), "+f"(c[3])
                 : "r"(a0), "r"(a1), "r"(a2), "r"(a3), "r"(b0), "r"(b1));
}

// ================== shared finalize (device function) ==================
__device__ void finalize_and_reset(float* smem, const float* __restrict__ proto,
                                   float* __restrict__ out, int t, int l, int w) {
    float* s_mean  = smem;                 // C*D
    float* s_proto = smem + C * D;         // C*D
    float* s_logit = smem + 2 * C * D;     // C*C

    for (int i = t; i < C * D; i += TPB) {
        int c = i / D;
        float cnt = (float)g_counts[c];
        s_mean[i]  = g_sums[i] / fmaxf(cnt, 1.0f);
        s_proto[i] = proto[i];
    }
    __syncthreads();

    for (int r = w; r < C; r += TPB / 32) {
        for (int jc = 0; jc < C; jc++) {
            float sacc = 0.f;
            #pragma unroll
            for (int kk = 0; kk < 8; kk++)
                sacc += s_mean[r * D + l + 32 * kk] * s_proto[jc * D + l + 32 * kk];
            #pragma unroll
            for (int o = 16; o; o >>= 1) sacc += __shfl_xor_sync(0xffffffffu, sacc, o);
            if (l == 0) s_logit[r * C + jc] = sacc * 10.0f;   // / TEMP (0.1)
        }
    }
    __syncthreads();

    if (t < 32) {
        float v = 0.f;
        if (t >= 1 && t < C) {
            float mx = -INFINITY;
            for (int jc = 0; jc < C; jc++) mx = fmaxf(mx, s_logit[t * C + jc]);
            float den = 0.f;
            for (int jc = 1; jc < C; jc++) den += expf(s_logit[t * C + jc] - mx);
            v = logf(den) - (s_logit[t * C + t] - mx);
        }
        #pragma unroll
        for (int o = 16; o; o >>= 1) v += __shfl_xor_sync(0xffffffffu, v, o);
        if (t == 0) out[0] = v / (float)(C - 1);
    }
    __syncthreads();

    for (int i = t; i < C * D; i += TPB) g_sums[i] = 0.f;
    if (t < C) g_counts[t] = 0;
    if (t == 0) g_done = 0;
}

// ============================================================
//  Warp-specialized TMA kernel
//  warps 0-15: SS + W-build for tile i; warps 16-31: MMA tile i-1
// ============================================================
#define SM_BUFA  0
#define SM_SLAB  (NSTAGE*TILE_FLOATS)                // 49152
#define SM_NRED  (SM_SLAB + NSTAGE*P)                // 49344
#define SM_NRED2 (SM_NRED + 2048)                    // 51392
#define SM_WT    (SM_NRED2 + 512)                    // 51904 (2 x 1632)
#define SM_SCNT  (SM_WT + 2*WT_FLOATS)               // 55168
#define SM_MBAR  (SM_SCNT + 32)                      // 55200
#define SM_TOTAL_FLOATS (SM_MBAR + 8)                // 55208
#define SMEM_BYTES (SM_TOTAL_FLOATS * 4)             // 220832

#define TILE_TX (2*32768 + P*4)       // 65792 bytes

__device__ __forceinline__ void issue_tile_tma(const CUtensorMap* map,
                                               const int* __restrict__ lab,
                                               float* bufA, int* slab, unsigned mbar,
                                               int b, int tile) {
    const int p0 = tile * P;
    mbar_expect(mbar, TILE_TX);
    unsigned d0 = s2u(bufA + b * TILE_FLOATS);
    tma2d(d0,          map, p0,      0, mbar);
    tma2d(d0 + 32768,  map, p0 + 32, 0, mbar);
    bulk_cp(slab + b * P, lab + p0, P * 4, mbar);
}

__global__ __launch_bounds__(TPB, 1)
void fused_tma(const __grid_constant__ CUtensorMap tmap,
               const int* __restrict__ lab,
               const float* __restrict__ proto, float* __restrict__ out) {
    extern __shared__ __align__(1024) float smem[];
    float*  bufA = smem + SM_BUFA;
    int*    slab = (int*)(smem + SM_SLAB);
    float*  nred = smem + SM_NRED;      // [32][64]
    float*  nred2= smem + SM_NRED2;     // [8][64]
    float*  wt   = smem + SM_WT;        // 2 x [24][68]
    int*    scnt = (int*)(smem + SM_SCNT);
    const unsigned mb0 = s2u(smem + SM_MBAR);

    const int t = threadIdx.x;
    const int l = t & 31, w = t >> 5;
    const int g = l >> 2, tk = l & 3;
    const bool is_norm = (t < 512);

    if (t < C) scnt[t] = 0;
    if (t == 0) {
        mbar_init(mb0, 1); mbar_init(mb0 + 8, 1); mbar_init(mb0 + 16, 1);
        asm volatile("fence.proxy.async.shared::cta;\n" ::: "memory");
    }
    __syncthreads();

    const int tl0 = blockIdx.x;
    if (t == TPB - 1) {                               // >=62 tiles/CTA, prologue safe
        issue_tile_tma(&tmap, lab, bufA, slab, mb0,      0, tl0);
        issue_tile_tma(&tmap, lab, bufA, slab, mb0 + 8,  1, tl0 + GRID);
        issue_tile_tma(&tmap, lab, bufA, slab, mb0 + 16, 2, tl0 + 2*GRID);
    }

    // norm-group mapping: p4 = pixel-quad 0..15, q = dim-slice 0..31 (8 rows each)
    const int p4 = t & 15;
    const int q  = (t >> 4) & 31;
    const int hss = p4 >> 3;
    const int c4s = (p4 & 7) * 4;

    // MMA-group mapping: warp w2 owns dims 16*w2..16*w2+15, all 64 pixels
    const int w2   = w - 16;
    const int rA   = 16 * (w2 < 0 ? 0 : w2) + g;
    const unsigned xorv = (unsigned)((rA & 7) << 2);

    float acc[3][4];
    #pragma unroll
    for (int n = 0; n < 3; n++)
        #pragma unroll
        for (int i = 0; i < 4; i++) acc[n][i] = 0.f;

    int i = 0, b = 0; unsigned ph = 0;
    int tl_last = tl0;
    for (int tl = tl0; tl < NTILES; tl += GRID, i++) {
        tl_last = tl;
        if (is_norm) {
            // ================= norm tile i (buffer b) =================
            mbar_wait(mb0 + 8 * b, ph);
            const float* tbase = bufA + b * TILE_FLOATS;

            {   // SS stage 1: partial squares for 4 pixels over 8 dims (rows q+32*jj)
                const float* hb = tbase + hss * HALF_FLOATS;
                float4 ss = make_float4(0.f, 0.f, 0.f, 0.f);
                #pragma unroll
                for (int jj = 0; jj < 8; jj++) {
                    int r = q + 32 * jj;
                    float4 v = *(const float4*)(hb + r * 32 + (c4s ^ ((r & 7) << 2)));
                    ss.x += v.x * v.x; ss.y += v.y * v.y;
                    ss.z += v.z * v.z; ss.w += v.w * v.w;
                }
                ((float4*)nred)[q * 16 + p4] = ss;
            }
            bar_norm();
            {   // fold 32 -> 8
                int p = t & 63, h = t >> 6;          // h 0..7
                nred2[h * 64 + p] = nred[(h * 4 + 0) * 64 + p] + nred[(h * 4 + 1) * 64 + p]
                                  + nred[(h * 4 + 2) * 64 + p] + nred[(h * 4 + 3) * 64 + p];
            }
            bar_norm();
            if (t < P) {   // finalize norm + build W column t directly
                float ssum = 0.f;
                #pragma unroll
                for (int h = 0; h < 8; h++) ssum += nred2[h * 64 + t];
                float inv = 1.0f / fmaxf(sqrtf(ssum), 1e-12f);
                int lv = slab[b * P + t];
                float* wdst = wt + (i & 1) * WT_FLOATS;
                #pragma unroll
                for (int n = 0; n < NB; n++)
                    wdst[n * WPITCH + t] = (lv == n) ? inv : 0.f;
                atomicAdd(&scnt[lv], 1);
            }
        } else if (i >= 1) {
            // ================= MMA tile i-1 (buffer (b+2)%3, wt[(i-1)&1]) =================
            const int pb = (b + 2) % 3;
            const float* pbase = bufA + pb * TILE_FLOATS;
            const float* wsrc  = wt + ((i - 1) & 1) * WT_FLOATS;
            const float* baseR  = pbase + rA * 32;
            const float* baseR8 = pbase + (rA + 8) * 32;
            #pragma unroll
            for (int kk = 0; kk < 8; kk++) {
                int k0  = kk * 8;
                int hof = (k0 >> 5) * HALF_FLOATS;
                int c   = k0 & 31;
                unsigned c1 = (unsigned)((c + tk) ^ (int)xorv) + hof;
                unsigned c2 = (unsigned)((c + tk + 4) ^ (int)xorv) + hof;
                unsigned a0 = __float_as_uint(baseR[c1]);
                unsigned a1 = __float_as_uint(baseR8[c1]);
                unsigned a2 = __float_as_uint(baseR[c2]);
                unsigned a3 = __float_as_uint(baseR8[c2]);
                #pragma unroll
                for (int n = 0; n < 3; n++) {
                    const float* wr = wsrc + (8 * n + g) * WPITCH;
                    unsigned b0 = __float_as_uint(wr[k0 + tk]);
                    unsigned b1 = __float_as_uint(wr[k0 + tk + 4]);
                    mma_tf32(acc[n], a0, a1, a2, a3, b0, b1);
                }
            }
        }
        __syncthreads();
        // refill buffer (b+2)%3 (= (i-1)%3) with tile tl + 2*GRID; both readers done
        if (t == TPB - 1 && i >= 1) {
            int nt = tl + 2 * GRID;
            if (nt < NTILES)
                issue_tile_tma(&tmap, lab, bufA, slab, mb0 + 8 * ((b + 2) % 3),
                               (b + 2) % 3, nt);
        }
        if (++b == NSTAGE) { b = 0; ph ^= 1u; }
    }

    // ---- epilogue: MMA for last tile (i = T, buffer (b+2)%3, wt[(T-1)&1]) ----
    if (!is_norm) {
        const int pb = (b + 2) % 3;
        const float* pbase = bufA + pb * TILE_FLOATS;
        const float* wsrc  = wt + ((i - 1) & 1) * WT_FLOATS;
        const float* baseR  = pbase + rA * 32;
        const float* baseR8 = pbase + (rA + 8) * 32;
        #pragma unroll
        for (int kk = 0; kk < 8; kk++) {
            int k0  = kk * 8;
            int hof = (k0 >> 5) * HALF_FLOATS;
            int c   = k0 & 31;
            unsigned c1 = (unsigned)((c + tk) ^ (int)xorv) + hof;
            unsigned c2 = (unsigned)((c + tk + 4) ^ (int)xorv) + hof;
            unsigned a0 = __float_as_uint(baseR[c1]);
            unsigned a1 = __float_as_uint(baseR8[c1]);
            unsigned a2 = __float_as_uint(baseR[c2]);
            unsigned a3 = __float_as_uint(baseR8[c2]);
            #pragma unroll
            for (int n = 0; n < 3; n++) {
                const float* wr = wsrc + (8 * n + g) * WPITCH;
                unsigned b0 = __float_as_uint(wr[k0 + tk]);
                unsigned b1 = __float_as_uint(wr[k0 + tk + 4]);
                mma_tf32(acc[n], a0, a1, a2, a3, b0, b1);
            }
        }
        // flush register accumulators (MMA warps only)
        const int dimA = rA, dimB = rA + 8;
        #pragma unroll
        for (int n = 0; n < 3; n++) {
            int cls0 = 8 * n + 2 * tk, cls1 = cls0 + 1;
            if (cls0 < C) {
                atomicAdd(&g_sums[cls0 * D + dimA], acc[n][0]);
                atomicAdd(&g_sums[cls0 * D + dimB], acc[n][2]);
            }
            if (cls1 < C) {
                atomicAdd(&g_sums[cls1 * D + dimA], acc[n][1]);
                atomicAdd(&g_sums[cls1 * D + dimB], acc[n][3]);
            }
        }
    }
    if (t < C) atomicAdd(&g_counts[t], scnt[t]);
    __syncthreads();

    if (t == 0) {
        __threadfence();
        scnt[31] = (atomicAdd(&g_done, 1u) == GRID - 1) ? 1 : 0;
    }
    __syncthreads();
    if (!scnt[31]) return;
    finalize_and_reset(smem, proto, out, t, l, w);
}

// ============================================================
//  Fallback kernel (bulk-copy path; used only if encode fails)
// ============================================================
#define FPITCH 68
#define FPITCH4 17
#define FB_BUFA  0
#define FB_SLAB  (NSTAGE*D*FPITCH)
#define FB_NRED  (FB_SLAB + NSTAGE*P)
#define FB_WT    FB_NRED
#define FB_NRED2 (FB_NRED + 4096)
#define FB_AUX   (FB_NRED2 + 1024)
#define FB_SCNT  (FB_AUX + 2*P)
#define FB_MBAR  (FB_SCNT + 32)
#define FB_TOTAL_FLOATS (FB_MBAR + 8)
#define FB_SMEM_BYTES (FB_TOTAL_FLOATS * 4)
#define FB_TILE_TX ((D + 1) * P * 4)

__device__ __forceinline__ void issue_tile_bulk(const float* __restrict__ feat,
                                                const int* __restrict__ lab,
                                                float* bufA, int* slab, unsigned mbar,
                                                int b, int tile, int t) {
    const int p0 = tile * P;
    if (t == TPB - 1) mbar_expect(mbar, FB_TILE_TX);
    if (t < D) {
        bulk_cp(bufA + b * (D * FPITCH) + t * FPITCH, feat + (size_t)t * N_PIX + p0,
                P * 4, mbar);
    } else if (t == D) {
        bulk_cp(slab + b * P, lab + p0, P * 4, mbar);
    }
}

__global__ __launch_bounds__(TPB, 1)
void fused_bulk(const float* __restrict__ feat, const int* __restrict__ lab,
                const float* __restrict__ proto, float* __restrict__ out) {
    extern __shared__ __align__(1024) float smem[];
    float*  bufA = smem + FB_BUFA;
    int*    slab = (int*)(smem + FB_SLAB);
    float*  nred = smem + FB_NRED;
    float*  wtf  = smem + FB_WT;
    float*  nred2= smem + FB_NRED2;
    float2* aux2 = (float2*)(smem + FB_AUX);
    int*    scnt = (int*)(smem + FB_SCNT);
    const unsigned mb0 = s2u(smem + FB_MBAR);

    const int t = threadIdx.x;
    const int l = t & 31, w = t >> 5;
    const int g = l >> 2, tk = l & 3;

    if (t < C) scnt[t] = 0;
    if (t == 0) {
        mbar_init(mb0, 1); mbar_init(mb0 + 8, 1); mbar_init(mb0 + 16, 1);
        asm volatile("fence.proxy.async.shared::cta;\n" ::: "memory");
    }
    __syncthreads();

    const int tl0 = blockIdx.x;
    issue_tile_bulk(feat, lab, bufA, slab, mb0,      0, tl0,          t);
    issue_tile_bulk(feat, lab, bufA, slab, mb0 + 8,  1, tl0 + GRID,   t);
    issue_tile_bulk(feat, lab, bufA, slab, mb0 + 16, 2, tl0 + 2*GRID, t);

    const int p4 = t & 15;
    const int q  = t >> 4;
    const int dim0  = 16 * (w & 15);
    const int kbase = (w >> 4) * 32;

    float acc[3][4];
    #pragma unroll
    for (int n = 0; n < 3; n++)
        #pragma unroll
        for (int i = 0; i < 4; i++) acc[n][i] = 0.f;

    int b = 0; unsigned ph = 0;
    for (int tl = tl0; tl < NTILES; tl += GRID) {
        mbar_wait(mb0 + 8 * b, ph);

        const float* tbase = bufA + b * (D * FPITCH);
        const int*   lb    = slab + b * P;

        {
            const float4* tb4 = (const float4*)tbase;
            float4 ss = make_float4(0.f, 0.f, 0.f, 0.f);
            #pragma unroll
            for (int jj = 0; jj < 4; jj++) {
                float4 v = tb4[(q * 4 + jj) * FPITCH4 + p4];
                ss.x += v.x * v.x; ss.y += v.y * v.y;
                ss.z += v.z * v.z; ss.w += v.w * v.w;
            }
            ((float4*)nred)[q * 16 + p4] = ss;
        }
        __syncthreads();
        {
            int p = t & 63, h = t >> 6;
            nred2[h * 64 + p] = nred[(h * 4 + 0) * 64 + p] + nred[(h * 4 + 1) * 64 + p]
                              + nred[(h * 4 + 2) * 64 + p] + nred[(h * 4 + 3) * 64 + p];
        }
        __syncthreads();
        if (t < P) {
            float ssum = 0.f;
            #pragma unroll
            for (int h = 0; h < 16; h++) ssum += nred2[h * 64 + t];
            float inv = 1.0f / fmaxf(sqrtf(ssum), 1e-12f);
            int lv = lb[t];
            aux2[t] = make_float2(inv, __int_as_float(lv));
            atomicAdd(&scnt[lv], 1);
        }
        __syncthreads();
        {
            {
                int n = t >> 6, kx = t & 63;
                float2 a = aux2[kx];
                wtf[n * FPITCH + kx] = (__float_as_int(a.y) == n) ? a.x : 0.f;
            }
            if (t < NB * P - TPB) {
                int idx = t + TPB;
                int n = idx >> 6, kx = idx & 63;
                float2 a = aux2[kx];
                wtf[n * FPITCH + kx] = (__float_as_int(a.y) == n) ? a.x : 0.f;
            }
        }
        __syncthreads();

        {
            const float* ar0 = tbase + (dim0 + g) * FPITCH;
            const float* ar1 = ar0 + 8 * FPITCH;
            #pragma unroll
            for (int kk = 0; kk < 4; kk++) {
                int k0 = kbase + kk * 8;
                unsigned a0 = __float_as_uint(ar0[k0 + tk]);
                unsigned a1 = __float_as_uint(ar1[k0 + tk]);
                unsigned a2 = __float_as_uint(ar0[k0 + tk + 4]);
                unsigned a3 = __float_as_uint(ar1[k0 + tk + 4]);
                #pragma unroll
                for (int n = 0; n < 3; n++) {
                    const float* wr = wtf + (8 * n + g) * FPITCH;
                    unsigned b0 = __float_as_uint(wr[k0 + tk]);
                    unsigned b1 = __float_as_uint(wr[k0 + tk + 4]);
                    mma_tf32(acc[n], a0, a1, a2, a3, b0, b1);
                }
            }
        }
        __syncthreads();

        int nt = tl + NSTAGE * GRID;
        if (nt < NTILES)
            issue_tile_bulk(feat, lab, bufA, slab, mb0 + 8 * b, b, nt, t);

        if (++b == NSTAGE) { b = 0; ph ^= 1u; }
    }

    {
        const int dimA = dim0 + g, dimB = dimA + 8;
        #pragma unroll
        for (int n = 0; n < 3; n++) {
            int cls0 = 8 * n + 2 * tk, cls1 = cls0 + 1;
            if (cls0 < C) {
                atomicAdd(&g_sums[cls0 * D + dimA], acc[n][0]);
                atomicAdd(&g_sums[cls0 * D + dimB], acc[n][2]);
            }
            if (cls1 < C) {
                atomicAdd(&g_sums[cls1 * D + dimA], acc[n][1]);
                atomicAdd(&g_sums[cls1 * D + dimB], acc[n][3]);
            }
        }
    }
    if (t < C) atomicAdd(&g_counts[t], scnt[t]);
    __syncthreads();

    if (t == 0) {
        __threadfence();
        scnt[31] = (atomicAdd(&g_done, 1u) == GRID - 1) ? 1 : 0;
    }
    __syncthreads();
    if (!scnt[31]) return;
    finalize_and_reset(smem, proto, out, t, l, w);
}

// ---------------- host: encode tensor map + launch ----------------
typedef CUresult (*encode_fn_t)(CUtensorMap*, CUtensorMapDataType, cuuint32_t, void*,
                                const cuuint64_t*, const cuuint64_t*,
                                const cuuint32_t*, const cuuint32_t*,
                                CUtensorMapInterleave, CUtensorMapSwizzle,
                                CUtensorMapL2promotion, CUtensorMapFloatOOBfill);

extern "C" void kernel_launch(void* const* d_in, const int* in_sizes, int n_in,
                              void* d_out, int out_size) {
    const float* feat  = (const float*)d_in[0];   // [1,256,768,768]
    const float* proto = (const float*)d_in[1];   // [21,256]
    // d_in[2] = outputs (unused by the loss)
    const int*   lab   = (const int*)d_in[3];     // [1,1,768,768]
    float* out = (float*)d_out;

    void* fn = nullptr;
    cudaDriverEntryPointQueryResult qr;
#if CUDART_VERSION >= 12050
    cudaGetDriverEntryPointByVersion("cuTensorMapEncodeTiled", &fn, 12000,
                                     cudaEnableDefault, &qr);
#endif
    if (!fn)
        cudaGetDriverEntryPoint("cuTensorMapEncodeTiled", &fn, cudaEnableDefault, &qr);

    bool tma_ok = false;
    CUtensorMap tmap;
    if (fn) {
        cuuint64_t dims[2]    = {(cuuint64_t)N_PIX, (cuuint64_t)D};
        cuuint64_t strides[1] = {(cuuint64_t)N_PIX * 4};
        cuuint32_t box[2]     = {32u, (cuuint32_t)D};
        cuuint32_t es[2]      = {1u, 1u};
        CUresult r = ((encode_fn_t)fn)(&tmap, CU_TENSOR_MAP_DATA_TYPE_FLOAT32, 2,
                                       (void*)feat, dims, strides, box, es,
                                       CU_TENSOR_MAP_INTERLEAVE_NONE,
                                       CU_TENSOR_MAP_SWIZZLE_128B,
                                       CU_TENSOR_MAP_L2_PROMOTION_L2_128B,
                                       CU_TENSOR_MAP_FLOAT_OOB_FILL_NONE);
        tma_ok = (r == CUDA_SUCCESS);
    }

    if (tma_ok) {
        cudaFuncSetAttribute(fused_tma,
                             cudaFuncAttributeMaxDynamicSharedMemorySize, SMEM_BYTES);
        fused_tma<<<GRID, TPB, SMEM_BYTES>>>(tmap, lab, proto, out);
    } else {
        cudaFuncSetAttribute(fused_bulk,
                             cudaFuncAttributeMaxDynamicSharedMemorySize, FB_SMEM_BYTES);
        fused_bulk<<<GRID, TPB, FB_SMEM_BYTES>>>(feat, lab, proto, out);
    }
}